// round 1
// baseline (speedup 1.0000x reference)
#include <cuda_runtime.h>
#include <cstdint>

#define TOKENS 16384
#define DIM    4096
#define NTHREADS 512
#define PER_THREAD (DIM / NTHREADS)   // 8
#define INPUT_SCALE 0.01f
#define EPS 1e-5f

// Block-wide reduction of two values (sum, sumsq). 512 threads = 16 warps.
__device__ __forceinline__ void block_reduce2(float& a, float& b) {
    __shared__ float sa[16], sb[16];
    const int lane = threadIdx.x & 31;
    const int wid  = threadIdx.x >> 5;
    #pragma unroll
    for (int off = 16; off > 0; off >>= 1) {
        a += __shfl_down_sync(0xFFFFFFFFu, a, off);
        b += __shfl_down_sync(0xFFFFFFFFu, b, off);
    }
    if (lane == 0) { sa[wid] = a; sb[wid] = b; }
    __syncthreads();
    if (wid == 0) {
        float x = (lane < 16) ? sa[lane] : 0.0f;
        float y = (lane < 16) ? sb[lane] : 0.0f;
        #pragma unroll
        for (int off = 8; off > 0; off >>= 1) {
            x += __shfl_down_sync(0xFFFFFFFFu, x, off);
            y += __shfl_down_sync(0xFFFFFFFFu, y, off);
        }
        if (lane == 0) { sa[0] = x; sb[0] = y; }
    }
    __syncthreads();
    a = sa[0];
    b = sb[0];
}

// One block per row. Single pass: dequant+add -> registers, reduce sum/sumsq,
// normalize+affine, write fp32 residual and quantized output.
// q_mode: 0 -> q written as float to qf_out; 1 -> q written as int8 to q8_out.
__global__ __launch_bounds__(NTHREADS, 2)
void dq_add_ln_q_kernel(const float* __restrict__ res,
                        const int*   __restrict__ qin,
                        const float* __restrict__ w,
                        const float* __restrict__ bias,
                        float* __restrict__ x_out,
                        float* __restrict__ qf_out,
                        int8_t* __restrict__ q8_out,
                        int q_mode) {
    const int row  = blockIdx.x;
    const int tid  = threadIdx.x;
    const long base = (long)row * DIM + tid * PER_THREAD;

    // Vectorized loads: 2x float4 + 2x int4 per thread
    const float4* res4 = reinterpret_cast<const float4*>(res + base);
    const int4*   qin4 = reinterpret_cast<const int4*>(qin + base);
    float4 r0 = res4[0];
    float4 r1 = res4[1];
    int4   i0 = qin4[0];
    int4   i1 = qin4[1];

    float v[PER_THREAD];
    v[0] = r0.x + (float)i0.x * INPUT_SCALE;
    v[1] = r0.y + (float)i0.y * INPUT_SCALE;
    v[2] = r0.z + (float)i0.z * INPUT_SCALE;
    v[3] = r0.w + (float)i0.w * INPUT_SCALE;
    v[4] = r1.x + (float)i1.x * INPUT_SCALE;
    v[5] = r1.y + (float)i1.y * INPUT_SCALE;
    v[6] = r1.z + (float)i1.z * INPUT_SCALE;
    v[7] = r1.w + (float)i1.w * INPUT_SCALE;

    float s = 0.0f, ss = 0.0f;
    #pragma unroll
    for (int j = 0; j < PER_THREAD; ++j) {
        s  += v[j];
        ss += v[j] * v[j];
    }
    block_reduce2(s, ss);

    const float inv_d = 1.0f / (float)DIM;
    const float mean  = s * inv_d;
    const float var   = fmaxf(ss * inv_d - mean * mean, 0.0f);
    const float rstd  = rsqrtf(var + EPS);

    // Write updated residual (x) — 2x float4
    float4* xo4 = reinterpret_cast<float4*>(x_out + base);
    xo4[0] = r0 = make_float4(v[0], v[1], v[2], v[3]);
    xo4[1] = r1 = make_float4(v[4], v[5], v[6], v[7]);

    // LayerNorm affine + requantize
    const float4* w4 = reinterpret_cast<const float4*>(w + tid * PER_THREAD);
    const float4* b4 = reinterpret_cast<const float4*>(bias + tid * PER_THREAD);
    float4 w0 = w4[0], w1 = w4[1];
    float4 b0 = b4[0], b1 = b4[1];

    float ln[PER_THREAD];
    ln[0] = (v[0] - mean) * rstd * w0.x + b0.x;
    ln[1] = (v[1] - mean) * rstd * w0.y + b0.y;
    ln[2] = (v[2] - mean) * rstd * w0.z + b0.z;
    ln[3] = (v[3] - mean) * rstd * w0.w + b0.w;
    ln[4] = (v[4] - mean) * rstd * w1.x + b1.x;
    ln[5] = (v[5] - mean) * rstd * w1.y + b1.y;
    ln[6] = (v[6] - mean) * rstd * w1.z + b1.z;
    ln[7] = (v[7] - mean) * rstd * w1.w + b1.w;

    float qv[PER_THREAD];
    #pragma unroll
    for (int j = 0; j < PER_THREAD; ++j) {
        qv[j] = fminf(fmaxf(rintf(ln[j]), -128.0f), 127.0f);
    }

    if (q_mode == 0) {
        // q as float32 (concatenated-fp32 output layout)
        float4* qo4 = reinterpret_cast<float4*>(qf_out + base);
        qo4[0] = make_float4(qv[0], qv[1], qv[2], qv[3]);
        qo4[1] = make_float4(qv[4], qv[5], qv[6], qv[7]);
    } else {
        // q as int8 (byte-packed output layout)
        int8_t p[8];
        #pragma unroll
        for (int j = 0; j < PER_THREAD; ++j) p[j] = (int8_t)(int)qv[j];
        // 8 contiguous bytes per thread, 8B-aligned
        *reinterpret_cast<uint64_t*>(q8_out + base) =
            *reinterpret_cast<const uint64_t*>(p);
    }
}

extern "C" void kernel_launch(void* const* d_in, const int* in_sizes, int n_in,
                              void* d_out, int out_size) {
    const float* res  = (const float*)d_in[0];   // residual_input_fp [T, D] fp32
    const int*   qin  = (const int*)d_in[1];     // input_int32       [T, D] int32
    const float* w    = (const float*)d_in[2];   // weight [D] fp32
    const float* bias = (const float*)d_in[3];   // bias   [D] fp32

    const long TD = (long)TOKENS * DIM;

    float*  x_out  = (float*)d_out;
    float*  qf_out = nullptr;
    int8_t* q8_out = nullptr;
    int q_mode;

    if ((long)out_size == 5 * TD) {
        // int8/byte-packed output: x fp32 raw bytes first, then q int8
        q_mode = 1;
        q8_out = (int8_t*)d_out + 4 * TD;
    } else {
        // default: fp32 output, x then q (as float), each T*D elements
        q_mode = 0;
        qf_out = (float*)d_out + TD;
    }

    dq_add_ln_q_kernel<<<TOKENS, NTHREADS>>>(res, qin, w, bias,
                                             x_out, qf_out, q8_out, q_mode);
}

// round 2
// speedup vs baseline: 1.0398x; 1.0398x over previous
#include <cuda_runtime.h>
#include <cstdint>

#define TOKENS 16384
#define DIM    4096
#define NTHREADS 512
#define NWARPS  (NTHREADS / 32)       // 16
#define PER_THREAD (DIM / NTHREADS)   // 8
#define INPUT_SCALE 0.01f
#define EPS 1e-5f

// One block per row. Single pass, single barrier:
//   load (streaming) -> dequant+add -> store x (streaming, pre-barrier)
//   -> warp partials -> smem -> one __syncthreads -> redundant final sum
//   -> normalize+affine -> quantize -> store q (streaming)
__global__ __launch_bounds__(NTHREADS, 3)
void dq_add_ln_q_kernel(const float* __restrict__ res,
                        const int*   __restrict__ qin,
                        const float* __restrict__ w,
                        const float* __restrict__ bias,
                        float* __restrict__ x_out,
                        float* __restrict__ qf_out,
                        int8_t* __restrict__ q8_out,
                        int q_mode) {
    __shared__ float2 part[NWARPS];

    const int row  = blockIdx.x;
    const int tid  = threadIdx.x;
    const int lane = tid & 31;
    const int wid  = tid >> 5;
    const long base = (long)row * DIM + tid * PER_THREAD;

    // Streaming (evict-first) vector loads: 2x float4 + 2x int4 per thread
    const float4 r0 = __ldcs(reinterpret_cast<const float4*>(res + base));
    const float4 r1 = __ldcs(reinterpret_cast<const float4*>(res + base) + 1);
    const int4   i0 = __ldcs(reinterpret_cast<const int4*>(qin + base));
    const int4   i1 = __ldcs(reinterpret_cast<const int4*>(qin + base) + 1);

    float v[PER_THREAD];
    v[0] = fmaf((float)i0.x, INPUT_SCALE, r0.x);
    v[1] = fmaf((float)i0.y, INPUT_SCALE, r0.y);
    v[2] = fmaf((float)i0.z, INPUT_SCALE, r0.z);
    v[3] = fmaf((float)i0.w, INPUT_SCALE, r0.w);
    v[4] = fmaf((float)i1.x, INPUT_SCALE, r1.x);
    v[5] = fmaf((float)i1.y, INPUT_SCALE, r1.y);
    v[6] = fmaf((float)i1.z, INPUT_SCALE, r1.z);
    v[7] = fmaf((float)i1.w, INPUT_SCALE, r1.w);

    // Store updated residual NOW — independent of the reduction, overlaps barrier.
    __stcs(reinterpret_cast<float4*>(x_out + base),
           make_float4(v[0], v[1], v[2], v[3]));
    __stcs(reinterpret_cast<float4*>(x_out + base) + 1,
           make_float4(v[4], v[5], v[6], v[7]));

    float s = 0.0f, ss = 0.0f;
    #pragma unroll
    for (int j = 0; j < PER_THREAD; ++j) {
        s  += v[j];
        ss = fmaf(v[j], v[j], ss);
    }

    // Warp-level reduction
    #pragma unroll
    for (int off = 16; off > 0; off >>= 1) {
        s  += __shfl_down_sync(0xFFFFFFFFu, s,  off);
        ss += __shfl_down_sync(0xFFFFFFFFu, ss, off);
    }
    if (lane == 0) part[wid] = make_float2(s, ss);
    __syncthreads();

    // Every thread redundantly sums the 16 warp partials (no second barrier).
    s = 0.0f; ss = 0.0f;
    #pragma unroll
    for (int i = 0; i < NWARPS; ++i) {
        float2 p = part[i];
        s += p.x; ss += p.y;
    }

    const float inv_d = 1.0f / (float)DIM;
    const float mean  = s * inv_d;
    const float var   = fmaxf(ss * inv_d - mean * mean, 0.0f);
    const float rstd  = rsqrtf(var + EPS);

    // LayerNorm affine params (heavily reused across rows -> default caching)
    const float4 w0 = __ldg(reinterpret_cast<const float4*>(w    + tid * PER_THREAD));
    const float4 w1 = __ldg(reinterpret_cast<const float4*>(w    + tid * PER_THREAD) + 1);
    const float4 b0 = __ldg(reinterpret_cast<const float4*>(bias + tid * PER_THREAD));
    const float4 b1 = __ldg(reinterpret_cast<const float4*>(bias + tid * PER_THREAD) + 1);

    float ln[PER_THREAD];
    ln[0] = fmaf((v[0] - mean) * rstd, w0.x, b0.x);
    ln[1] = fmaf((v[1] - mean) * rstd, w0.y, b0.y);
    ln[2] = fmaf((v[2] - mean) * rstd, w0.z, b0.z);
    ln[3] = fmaf((v[3] - mean) * rstd, w0.w, b0.w);
    ln[4] = fmaf((v[4] - mean) * rstd, w1.x, b1.x);
    ln[5] = fmaf((v[5] - mean) * rstd, w1.y, b1.y);
    ln[6] = fmaf((v[6] - mean) * rstd, w1.z, b1.z);
    ln[7] = fmaf((v[7] - mean) * rstd, w1.w, b1.w);

    float qv[PER_THREAD];
    #pragma unroll
    for (int j = 0; j < PER_THREAD; ++j) {
        qv[j] = fminf(fmaxf(rintf(ln[j]), -128.0f), 127.0f);
    }

    if (q_mode == 0) {
        // q as float32 (concatenated-fp32 output layout)
        __stcs(reinterpret_cast<float4*>(qf_out + base),
               make_float4(qv[0], qv[1], qv[2], qv[3]));
        __stcs(reinterpret_cast<float4*>(qf_out + base) + 1,
               make_float4(qv[4], qv[5], qv[6], qv[7]));
    } else {
        // q as int8 (byte-packed output layout)
        int8_t p[8];
        #pragma unroll
        for (int j = 0; j < PER_THREAD; ++j) p[j] = (int8_t)(int)qv[j];
        __stcs(reinterpret_cast<unsigned long long*>(q8_out + base),
               *reinterpret_cast<const unsigned long long*>(p));
    }
}

extern "C" void kernel_launch(void* const* d_in, const int* in_sizes, int n_in,
                              void* d_out, int out_size) {
    const float* res  = (const float*)d_in[0];   // residual_input_fp [T, D] fp32
    const int*   qin  = (const int*)d_in[1];     // input_int32       [T, D] int32
    const float* w    = (const float*)d_in[2];   // weight [D] fp32
    const float* bias = (const float*)d_in[3];   // bias   [D] fp32

    const long TD = (long)TOKENS * DIM;

    float*  x_out  = (float*)d_out;
    float*  qf_out = nullptr;
    int8_t* q8_out = nullptr;
    int q_mode;

    if ((long)out_size == 5 * TD) {
        // int8/byte-packed output: x fp32 raw bytes first, then q int8
        q_mode = 1;
        q8_out = (int8_t*)d_out + 4 * TD;
    } else {
        // default: fp32 output, x then q (as float), each T*D elements
        q_mode = 0;
        qf_out = (float*)d_out + TD;
    }

    dq_add_ln_q_kernel<<<TOKENS, NTHREADS>>>(res, qin, w, bias,
                                             x_out, qf_out, q8_out, q_mode);
}